// round 8
// baseline (speedup 1.0000x reference)
#include <cuda_runtime.h>
#include <math.h>
#include <stdint.h>

#define LAYERS 8
#define H      1024
#define NH     16
#define KVH    4
#define HD     64
#define INTER  2816
#define VOCAB  32000
#define CTX    2048
#define EPS    1e-5f

#define NBLOCKS 148
#define ACHUNKS 8
#define QKV_R   1536
#define GU_R    5632
#define QB      159744u     // qkv region byte offset (39*4096)
#define DB      28672u      // down region byte offset (7*4096)
#define LMB     49152u      // lm tile stride (12 rows * 4KB)
#define SMEM_FLOATS 55136   // 220544 bytes dynamic smem

// ---------------------------------------------------------------------------
__device__ __align__(16) float g_hid[H];
__device__ __align__(16) float g_qkv[QKV_R];
__device__ __align__(16) float g_gu[GU_R];
__device__ float g_am[NH][ACHUNKS];
__device__ float g_as[NH][ACHUNKS];
__device__ __align__(16) float g_ao[NH][ACHUNKS][HD];
__device__ float    g_lmv[NBLOCKS];
__device__ int      g_lmi[NBLOCKS];
__device__ unsigned g_barcnt;
__device__ unsigned g_bargen;

// ---------------------------------------------------------------------------
__device__ __forceinline__ uint32_t s2u(const void* p) {
    return (uint32_t)__cvta_generic_to_shared(p);
}
__device__ __forceinline__ void mbar_init(uint32_t mb) {
    asm volatile("mbarrier.init.shared.b64 [%0], %1;" :: "r"(mb), "r"(1u) : "memory");
}
__device__ __forceinline__ void mbar_expect(uint32_t mb, uint32_t bytes) {
    asm volatile("mbarrier.arrive.expect_tx.shared.b64 _, [%0], %1;"
                 :: "r"(mb), "r"(bytes) : "memory");
}
__device__ __forceinline__ void mbar_wait(uint32_t mb, unsigned parity) {
    asm volatile(
        "{\n\t.reg .pred P;\n\t"
        "LAB_W%=:\n\t"
        "mbarrier.try_wait.parity.acquire.cta.shared::cta.b64 P, [%0], %1, 0x989680;\n\t"
        "@P bra LAB_D%=;\n\t"
        "bra LAB_W%=;\n\t"
        "LAB_D%=:\n\t}"
        :: "r"(mb), "r"(parity) : "memory");
}
__device__ __forceinline__ void bulk_cp(uint32_t dst, const float* src,
                                        uint32_t bytes, uint32_t mb) {
    asm volatile(
        "cp.async.bulk.shared::cluster.global.mbarrier::complete_tx::bytes [%0], [%1], %2, [%3];"
        :: "r"(dst), "l"(src), "r"(bytes), "r"(mb) : "memory");
}

// ring chunk wait (all threads; seqW block-uniform)
__device__ __forceinline__ void wait_chunk(unsigned& seqW, unsigned long long* mbars) {
    uint32_t mb = s2u(mbars + (seqW & 15));
    mbar_wait(mb, (seqW >> 4) & 1);
    seqW++;
}
// single-segment issue
__device__ __forceinline__ void issue_seg(unsigned& seqI, unsigned long long* mbars,
                                          int tid, char* slabB, uint32_t dstB,
                                          const float* src, uint32_t bytes) {
    if (tid == 0) {
        uint32_t mb = s2u(mbars + (seqI & 15));
        mbar_expect(mb, bytes);
        bulk_cp(s2u(slabB + dstB), src, bytes, mb);
    }
    seqI++;
}

// ---------------------------------------------------------------------------
__device__ __forceinline__ void grid_sync() {
    __syncthreads();
    if (threadIdx.x == 0) {
        __threadfence();
        unsigned gen = *(volatile unsigned*)&g_bargen;
        if (atomicAdd(&g_barcnt, 1u) == NBLOCKS - 1) {
            g_barcnt = 0;
            __threadfence();
            atomicAdd(&g_bargen, 1u);
        } else {
            while (*(volatile unsigned*)&g_bargen == gen) { }
            __threadfence();
        }
    }
    __syncthreads();
}

__device__ __forceinline__ float block_rsum(float v, float* red) {
    int lane = threadIdx.x & 31, wid = threadIdx.x >> 5;
    #pragma unroll
    for (int o = 16; o; o >>= 1) v += __shfl_xor_sync(~0u, v, o);
    if (lane == 0) red[wid] = v;
    __syncthreads();
    if (threadIdx.x == 0) {
        float t = 0.f;
        #pragma unroll
        for (int i = 0; i < 32; i++) t += red[i];
        red[0] = t;
    }
    __syncthreads();
    float r = red[0];
    __syncthreads();
    return r;
}
__device__ __forceinline__ float block_rmax(float v, float* red) {
    int lane = threadIdx.x & 31, wid = threadIdx.x >> 5;
    #pragma unroll
    for (int o = 16; o; o >>= 1) v = fmaxf(v, __shfl_xor_sync(~0u, v, o));
    if (lane == 0) red[wid] = v;
    __syncthreads();
    if (threadIdx.x == 0) {
        float t = red[0];
        #pragma unroll
        for (int i = 1; i < 32; i++) t = fmaxf(t, red[i]);
        red[0] = t;
    }
    __syncthreads();
    float r = red[0];
    __syncthreads();
    return r;
}
__device__ __forceinline__ float d4(float4 w, float4 a) {
    return w.x * a.x + w.y * a.y + w.z * a.z + w.w * a.w;
}
__device__ __forceinline__ float warp_red(float s) {
    #pragma unroll
    for (int o = 16; o; o >>= 1) s += __shfl_xor_sync(~0u, s, o);
    return s;
}

// ---------------------------------------------------------------------------
__global__ void __launch_bounds__(1024, 1)
decode_k(const float* __restrict__ embed,  const float* __restrict__ q_w,
         const float* __restrict__ k_w,    const float* __restrict__ v_w,
         const float* __restrict__ o_w,    const float* __restrict__ gate_w,
         const float* __restrict__ up_w,   const float* __restrict__ down_w,
         const float* __restrict__ ln1_w,  const float* __restrict__ ln2_w,
         const float* __restrict__ norm_w, const float* __restrict__ lm_head,
         const float* __restrict__ kv,     const float* __restrict__ cosc,
         const float* __restrict__ sinc,   const int* __restrict__ input_ids,
         const int* __restrict__ pos_ids,  float* __restrict__ out) {
    extern __shared__ __align__(16) float smem[];
    float* xs = smem;                       // [1024]
    float* un = smem + 1024;                // [2816] union: xm | attention bufs
    float* xm = un;
    float* sc = un;                         // [256]
    float* qs = un + 256;                   // [64]
    float* kn = un + 320;                   // [64]
    float* vn = un + 384;                   // [64]
    float* part = un + 448;                 // [32*64]
    float* red = smem + 3840;               // [32]
    int*   redi = (int*)(smem + 3872);      // [32]
    unsigned long long* mbars = (unsigned long long*)(smem + 3904); // [16]
    float* slab = smem + 3936;              // 51200 floats (200KB)
    char*  slabB = (char*)slab;

    const int tid = threadIdx.x, lane = tid & 31, wid = tid >> 5;
    const int bid = blockIdx.x;

    const int r0q = (QKV_R * bid) / NBLOCKS, r1q = (QKV_R * (bid + 1)) / NBLOCKS;
    const int r0o = (H * bid) / NBLOCKS,     r1o = (H * (bid + 1)) / NBLOCKS;
    const int r0g = (GU_R * bid) / NBLOCKS,  r1g = (GU_R * (bid + 1)) / NBLOCKS;
    const int r0L = (VOCAB * bid) / NBLOCKS, r1L = (VOCAB * (bid + 1)) / NBLOCKS;
    const int nq = r1q - r0q, no = r1o - r0o, ng = r1g - r0g;

    unsigned seqI = 0, seqW = 0;

    if (tid < 16) mbar_init(s2u(mbars + tid));
    __syncthreads();
    asm volatile("fence.proxy.async.shared::cta;" ::: "memory");

    if (bid == 0) g_hid[tid] = embed[(size_t)input_ids[0] * H + tid];

    // ---- issue qkv for layer 0 (4 chunks into QB region) ----
    #pragma unroll 1
    for (int c = 0; c < 4; c++) {
        int a = r0q + (nq * c) / 4, b = r0q + (nq * (c + 1)) / 4;
        if (tid == 0) {
            uint32_t mb = s2u(mbars + (seqI & 15));
            mbar_expect(mb, (uint32_t)(b - a) * 4096u);
            int r = a;
            while (r < b) {
                const float* src; int lim;
                if (r < H)            { src = q_w + (size_t)r * H; lim = min(b, H); }
                else if (r < H + 256) { src = k_w + (size_t)(r - H) * H; lim = min(b, H + 256); }
                else                  { src = v_w + (size_t)(r - H - 256) * H; lim = b; }
                bulk_cp(s2u(slabB + QB + (size_t)(r - r0q) * 4096), src,
                        (uint32_t)(lim - r) * 4096u, mb);
                r = lim;
            }
        }
        seqI++;
    }
    grid_sync();

    const int pos = pos_ids[0];
    const int cl = (pos + ACHUNKS) >> 3;

    for (int l = 0; l < LAYERS; l++) {
        // =========== S1: rms1; issue o + guA; wait/compute qkv ===========
        float hv = g_hid[tid];
        xs[tid] = hv * ln1_w[(size_t)l * H + tid];
        float ssq = block_rsum(hv * hv, red);
        float rs = rsqrtf(ssq / (float)H + EPS);

        // issue o (1 chunk @0)
        issue_seg(seqI, mbars, tid, slabB, 0u,
                  o_w + (size_t)l * H * H + (size_t)r0o * H, (uint32_t)no * 4096u);
        // issue guA: local rows [7, ng) @ i*4096 (4 chunks)
        #pragma unroll 1
        for (int c = 0; c < 4; c++) {
            int a = 7 + ((ng - 7) * c) / 4, b = 7 + ((ng - 7) * (c + 1)) / 4;
            if (tid == 0) {
                uint32_t mb = s2u(mbars + (seqI & 15));
                mbar_expect(mb, (uint32_t)(b - a) * 4096u);
                int i = a;
                while (i < b) {
                    int u = r0g + i;
                    const float* src; int lim;
                    if (u < INTER) { src = gate_w + (size_t)l * INTER * H + (size_t)u * H;
                                     lim = min(b, INTER - r0g); }
                    else           { src = up_w + (size_t)l * INTER * H + (size_t)(u - INTER) * H;
                                     lim = b; }
                    bulk_cp(s2u(slabB + (size_t)i * 4096), src,
                            (uint32_t)(lim - i) * 4096u, mb);
                    i = lim;
                }
            }
            seqI++;
        }

        // wait/compute qkv (4 chunks)
        const float4* x4 = (const float4*)xs;
        #pragma unroll 1
        for (int c = 0; c < 4; c++) {
            int a = r0q + (nq * c) / 4, b = r0q + (nq * (c + 1)) / 4;
            wait_chunk(seqW, mbars);
            for (int r = a + wid; r < b; r += 32) {
                const float4* w4 = (const float4*)(slabB + QB + (size_t)(r - r0q) * 4096);
                float s = 0.f;
                #pragma unroll
                for (int k = 0; k < 8; k++) { int i = lane + k * 32; s += d4(w4[i], x4[i]); }
                s = warp_red(s);
                if (lane == 0) g_qkv[r] = s * rs;
            }
        }
        grid_sync();

        // =========== S2: attention (flash-decode) ===========
        if (bid < NH * ACHUNKS) {
            int head = bid >> 3, ch = bid & (ACHUNKS - 1), kvh = head >> 2;
            int j0 = ch * cl;
            int j1 = min(j0 + cl, pos + 1);
            int n = j1 - j0;

            if (tid < HD) {
                float c  = cosc[(size_t)pos * HD + tid];
                float sn = sinc[(size_t)pos * HD + tid];
                float q0 = g_qkv[head * HD + tid];
                float qr = g_qkv[head * HD + ((tid < HD / 2) ? tid + HD / 2 : tid - HD / 2)];
                if (tid < HD / 2) qr = -qr;
                qs[tid] = q0 * c + qr * sn;
                float k0 = g_qkv[H + kvh * HD + tid];
                float kr = g_qkv[H + kvh * HD + ((tid < HD / 2) ? tid + HD / 2 : tid - HD / 2)];
                if (tid < HD / 2) kr = -kr;
                kn[tid] = k0 * c + kr * sn;
                vn[tid] = g_qkv[H + KVH * HD + kvh * HD + tid];
            }
            __syncthreads();

            const float* K = kv + (size_t)l * KVH * CTX * HD + (size_t)kvh * CTX * HD;
            const float* V = kv + (size_t)(LAYERS + l) * KVH * CTX * HD + (size_t)kvh * CTX * HD;
            const float4* q4 = (const float4*)qs;

            int half = lane >> 4, hl = lane & 15;
            for (int jb = j0 + wid * 2; jb < j1; jb += 64) {
                int j = jb + half;
                bool valid = (j < j1);
                const float4* k4;
                if (!valid)        k4 = (const float4*)kn;
                else if (j == pos) k4 = (const float4*)kn;
                else               k4 = (const float4*)(K + (size_t)j * HD);
                float4 a = q4[hl], b = k4[hl];
                float s = a.x * b.x + a.y * b.y + a.z * b.z + a.w * b.w;
                #pragma unroll
                for (int o = 8; o; o >>= 1) s += __shfl_xor_sync(~0u, s, o);
                if (hl == 0 && valid) sc[j - j0] = s * 0.125f;
            }
            __syncthreads();

            float m = -1e30f;
            if (tid < n) m = sc[tid];
            float M = block_rmax(m, red);
            float e = 0.f;
            if (tid < n) { e = __expf(sc[tid] - M); sc[tid] = e; }
            float S = block_rsum(e, red);

            float a0 = 0.f, a1 = 0.f;
            for (int j = j0 + wid; j < j1; j += 32) {
                float p = sc[j - j0];
                const float* Vr = (j == pos) ? (const float*)vn : V + (size_t)j * HD;
                a0 += p * Vr[lane];
                a1 += p * Vr[lane + 32];
            }
            part[wid * HD + lane]      = a0;
            part[wid * HD + lane + 32] = a1;
            __syncthreads();
            if (tid == 0) { g_am[head][ch] = (n > 0) ? M : -1e30f; g_as[head][ch] = S; }
            if (tid < HD) {
                float t = 0.f;
                #pragma unroll
                for (int w = 0; w < 32; w++) t += part[w * HD + tid];
                g_ao[head][ch][tid] = t;
            }
        }
        grid_sync();

        // =========== S3: combine attention; wait/compute o; issue guB ===========
        {
            int head = tid >> 6, d = tid & (HD - 1);
            float M = -1e30f;
            #pragma unroll
            for (int c = 0; c < ACHUNKS; c++) M = fmaxf(M, g_am[head][c]);
            float S = 0.f, o = 0.f;
            #pragma unroll
            for (int c = 0; c < ACHUNKS; c++) {
                float e = __expf(g_am[head][c] - M);
                S += g_as[head][c] * e;
                o += g_ao[head][c][d] * e;
            }
            xs[tid] = o / S;
        }
        __syncthreads();

        wait_chunk(seqW, mbars);    // o
        for (int r = r0o + wid; r < r1o; r += 32) {
            const float4* w4 = (const float4*)(slabB + (size_t)(r - r0o) * 4096);
            float s = 0.f;
            #pragma unroll
            for (int k = 0; k < 8; k++) { int i = lane + k * 32; s += d4(w4[i], x4[i]); }
            s = warp_red(s);
            if (lane == 0) g_hid[r] += s;
        }
        __syncthreads();   // all warps done reading [0,28K) before guB overwrites
        // issue guB: local rows [0,7) @ i*4096
        {
            if (tid == 0) {
                uint32_t mb = s2u(mbars + (seqI & 15));
                mbar_expect(mb, 7u * 4096u);
                int i = 0;
                while (i < 7) {
                    int u = r0g + i;
                    const float* src; int lim;
                    if (u < INTER) { src = gate_w + (size_t)l * INTER * H + (size_t)u * H;
                                     lim = min(7, INTER - r0g); }
                    else           { src = up_w + (size_t)l * INTER * H + (size_t)(u - INTER) * H;
                                     lim = 7; }
                    bulk_cp(s2u(slabB + (size_t)i * 4096), src,
                            (uint32_t)(lim - i) * 4096u, mb);
                    i = lim;
                }
            }
            seqI++;
        }
        grid_sync();

        // =========== S4: rms2; wait/compute gu; issue down ===========
        hv = g_hid[tid];
        xs[tid] = hv * ln2_w[(size_t)l * H + tid];
        ssq = block_rsum(hv * hv, red);
        float rs2 = rsqrtf(ssq / (float)H + EPS);

        #pragma unroll 1
        for (int c = 0; c < 4; c++) {           // guA local rows [7, ng)
            int a = 7 + ((ng - 7) * c) / 4, b = 7 + ((ng - 7) * (c + 1)) / 4;
            wait_chunk(seqW, mbars);
            for (int i = a + wid; i < b; i += 32) {
                const float4* w4 = (const float4*)(slabB + (size_t)i * 4096);
                float s = 0.f;
                #pragma unroll
                for (int k = 0; k < 8; k++) { int ii = lane + k * 32; s += d4(w4[ii], x4[ii]); }
                s = warp_red(s);
                if (lane == 0) g_gu[r0g + i] = s * rs2;
            }
        }
        wait_chunk(seqW, mbars);                 // guB local rows [0,7)
        for (int i = wid; i < 7; i += 32) {
            const float4* w4 = (const float4*)(slabB + (size_t)i * 4096);
            float s = 0.f;
            #pragma unroll
            for (int k = 0; k < 8; k++) { int ii = lane + k * 32; s += d4(w4[ii], x4[ii]); }
            s = warp_red(s);
            if (lane == 0) g_gu[r0g + i] = s * rs2;
        }
        __syncthreads();   // region [28K,...) free before down copy overwrites
        #pragma unroll 1
        for (int c = 0; c < 4; c++) {            // down rows [r0o,r1o), 4 chunks
            int a = r0o + (no * c) / 4, b = r0o + (no * (c + 1)) / 4;
            issue_seg(seqI, mbars, tid, slabB, DB + (uint32_t)(a - r0o) * 11264u,
                      down_w + (size_t)l * H * INTER + (size_t)a * INTER,
                      (uint32_t)(b - a) * 11264u);
        }
        grid_sync();

        // =========== S5: issue next qkv; build xm; wait/compute down ===========
        if (l + 1 < LAYERS) {
            #pragma unroll 1
            for (int c = 0; c < 4; c++) {
                int a = r0q + (nq * c) / 4, b = r0q + (nq * (c + 1)) / 4;
                if (tid == 0) {
                    uint32_t mb = s2u(mbars + (seqI & 15));
                    mbar_expect(mb, (uint32_t)(b - a) * 4096u);
                    int r = a;
                    while (r < b) {
                        const float* src; int lim;
                        if (r < H)            { src = q_w + (size_t)(l + 1) * H * H + (size_t)r * H; lim = min(b, H); }
                        else if (r < H + 256) { src = k_w + (size_t)(l + 1) * 256 * H + (size_t)(r - H) * H; lim = min(b, H + 256); }
                        else                  { src = v_w + (size_t)(l + 1) * 256 * H + (size_t)(r - H - 256) * H; lim = b; }
                        bulk_cp(s2u(slabB + QB + (size_t)(r - r0q) * 4096), src,
                                (uint32_t)(lim - r) * 4096u, mb);
                        r = lim;
                    }
                }
                seqI++;
            }
        }
        for (int i = tid; i < INTER; i += 1024) {
            float g = g_gu[i];
            float u = g_gu[INTER + i];
            xm[i] = (g / (1.f + __expf(-g))) * u;
        }
        __syncthreads();

        const float4* xm4 = (const float4*)xm;
        #pragma unroll 1
        for (int c = 0; c < 4; c++) {
            int a = r0o + (no * c) / 4, b = r0o + (no * (c + 1)) / 4;
            wait_chunk(seqW, mbars);
            for (int r = a + wid; r < b; r += 32) {
                const float4* w4 = (const float4*)(slabB + DB + (size_t)(r - r0o) * 11264);
                float s = 0.f;
                for (int i = lane; i < INTER / 4; i += 32) s += d4(w4[i], xm4[i]);
                s = warp_red(s);
                if (lane == 0) g_hid[r] += s;
            }
        }
        grid_sync();
    }

    // =========== final norm + streamed lm_head + argmax ===========
    {
        float hv = g_hid[tid];
        xs[tid] = hv * norm_w[tid];
        float ssq = block_rsum(hv * hv, red);
        float rsf = rsqrtf(ssq / (float)H + EPS);

        int nL = r1L - r0L;
        int nch = (nL + 11) / 12;
        for (int c = 0; c < nch && c < 4; c++) {
            int a = r0L + c * 12, b = min(a + 12, r1L);
            issue_seg(seqI, mbars, tid, slabB, (uint32_t)(c & 3) * LMB,
                      lm_head + (size_t)a * H, (uint32_t)(b - a) * 4096u);
        }

        float bv = -1e30f;
        int   bi = 0x7fffffff;
        const float4* x4 = (const float4*)xs;
        #pragma unroll 1
        for (int c = 0; c < nch; c++) {
            wait_chunk(seqW, mbars);
            int a = r0L + c * 12, b = min(a + 12, r1L);
            const char* base = slabB + (size_t)(c & 3) * LMB;
            for (int r = a + wid; r < b; r += 32) {
                const float4* w4 = (const float4*)(base + (size_t)(r - a) * 4096);
                float s = 0.f;
                #pragma unroll
                for (int k = 0; k < 8; k++) { int i = lane + k * 32; s += d4(w4[i], x4[i]); }
                s = warp_red(s) * rsf;
                if (s > bv || (s == bv && r < bi)) { bv = s; bi = r; }
            }
            __syncthreads();   // buffer free before reuse
            if (c + 4 < nch) {
                int a2 = r0L + (c + 4) * 12, b2 = min(a2 + 12, r1L);
                issue_seg(seqI, mbars, tid, slabB, (uint32_t)((c + 4) & 3) * LMB,
                          lm_head + (size_t)a2 * H, (uint32_t)(b2 - a2) * 4096u);
            }
        }

        if (lane == 0) { red[wid] = bv; redi[wid] = bi; }
        __syncthreads();
        if (tid == 0) {
            float b = red[0]; int ii = redi[0];
            #pragma unroll
            for (int i = 1; i < 32; i++)
                if (red[i] > b || (red[i] == b && redi[i] < ii)) { b = red[i]; ii = redi[i]; }
            g_lmv[bid] = b;
            g_lmi[bid] = ii;
        }
        grid_sync();
        if (bid == 0 && tid == 0) {
            float b = g_lmv[0]; int ii = g_lmi[0];
            for (int i = 1; i < NBLOCKS; i++) {
                float v = g_lmv[i]; int id = g_lmi[i];
                if (v > b || (v == b && id < ii)) { b = v; ii = id; }
            }
            out[0] = (float)ii;
            out[1] = b;
        }
    }
}

// ---------------------------------------------------------------------------
extern "C" void kernel_launch(void* const* d_in, const int* in_sizes, int n_in,
                              void* d_out, int out_size) {
    const float* embed   = (const float*)d_in[0];
    const float* q_w     = (const float*)d_in[1];
    const float* k_w     = (const float*)d_in[2];
    const float* v_w     = (const float*)d_in[3];
    const float* o_w     = (const float*)d_in[4];
    const float* gate_w  = (const float*)d_in[5];
    const float* up_w    = (const float*)d_in[6];
    const float* down_w  = (const float*)d_in[7];
    const float* ln1_w   = (const float*)d_in[8];
    const float* ln2_w   = (const float*)d_in[9];
    const float* norm_w  = (const float*)d_in[10];
    const float* lm_head = (const float*)d_in[11];
    const float* kv      = (const float*)d_in[12];
    const float* cosc    = (const float*)d_in[13];
    const float* sinc    = (const float*)d_in[14];
    const int* input_ids = (const int*)d_in[17];
    const int* pos_ids   = (const int*)d_in[18];

    static bool attr_set = false;
    if (!attr_set) {
        cudaFuncSetAttribute(decode_k, cudaFuncAttributeMaxDynamicSharedMemorySize,
                             SMEM_FLOATS * 4);
        attr_set = true;
    }

    decode_k<<<NBLOCKS, 1024, SMEM_FLOATS * 4>>>(
        embed, q_w, k_w, v_w, o_w, gate_w, up_w, down_w,
        ln1_w, ln2_w, norm_w, lm_head, kv, cosc, sinc,
        input_ids, pos_ids, (float*)d_out);
}

// round 9
// speedup vs baseline: 1.0796x; 1.0796x over previous
#include <cuda_runtime.h>
#include <math.h>
#include <stdint.h>

#define LAYERS 8
#define H      1024
#define NH     16
#define KVH    4
#define HD     64
#define INTER  2816
#define VOCAB  32000
#define CTX    2048
#define EPS    1e-5f

#define NBLOCKS 148
#define ACHUNKS 8
#define QKV_R   1536
#define GU_R    5632
#define QKVB    163840u      // qkv region byte offset in slab (40 rows * 4KB)
#define LMB     49152u       // lm tile stride (12 rows * 4KB)
#define SMEM_FLOATS 56192    // 224768 bytes dynamic smem

// ---------------------------------------------------------------------------
__device__ __align__(16) float g_hid[H];
__device__ __align__(16) float g_qkv[QKV_R];
__device__ __align__(16) float g_gu[GU_R];
__device__ float g_am[NH][ACHUNKS];
__device__ float g_as[NH][ACHUNKS];
__device__ __align__(16) float g_ao[NH][ACHUNKS][HD];
__device__ float    g_lmv[NBLOCKS];
__device__ int      g_lmi[NBLOCKS];
__device__ unsigned g_barcnt;
__device__ unsigned g_bargen;

// ---------------------------------------------------------------------------
__device__ __forceinline__ uint32_t s2u(const void* p) {
    return (uint32_t)__cvta_generic_to_shared(p);
}
__device__ __forceinline__ void mbar_init(uint32_t mb) {
    asm volatile("mbarrier.init.shared.b64 [%0], %1;" :: "r"(mb), "r"(1u) : "memory");
}
__device__ __forceinline__ void mbar_expect(uint32_t mb, uint32_t bytes) {
    asm volatile("mbarrier.arrive.expect_tx.shared.b64 _, [%0], %1;"
                 :: "r"(mb), "r"(bytes) : "memory");
}
__device__ __forceinline__ void mbar_wait(uint32_t mb, unsigned parity) {
    asm volatile(
        "{\n\t.reg .pred P;\n\t"
        "LAB_W%=:\n\t"
        "mbarrier.try_wait.parity.acquire.cta.shared::cta.b64 P, [%0], %1, 0x989680;\n\t"
        "@P bra LAB_D%=;\n\t"
        "bra LAB_W%=;\n\t"
        "LAB_D%=:\n\t}"
        :: "r"(mb), "r"(parity) : "memory");
}
__device__ __forceinline__ void bulk_cp(uint32_t dst, const float* src,
                                        uint32_t bytes, uint32_t mb) {
    asm volatile(
        "cp.async.bulk.shared::cluster.global.mbarrier::complete_tx::bytes [%0], [%1], %2, [%3];"
        :: "r"(dst), "l"(src), "r"(bytes), "r"(mb) : "memory");
}
__device__ __forceinline__ void wait_chunk(unsigned& seqW, unsigned long long* mbars) {
    uint32_t mb = s2u(mbars + (seqW & 15));
    mbar_wait(mb, (seqW >> 4) & 1);
    seqW++;
}
__device__ __forceinline__ void issue_seg(unsigned& seqI, unsigned long long* mbars,
                                          int tid, char* slabB, uint32_t dstB,
                                          const float* src, uint32_t bytes) {
    if (tid == 0) {
        uint32_t mb = s2u(mbars + (seqI & 15));
        mbar_expect(mb, bytes);
        bulk_cp(s2u(slabB + dstB), src, bytes, mb);
    }
    seqI++;
}

// ---------------------------------------------------------------------------
__device__ __forceinline__ void grid_sync() {
    __syncthreads();
    if (threadIdx.x == 0) {
        __threadfence();
        unsigned gen = *(volatile unsigned*)&g_bargen;
        if (atomicAdd(&g_barcnt, 1u) == NBLOCKS - 1) {
            g_barcnt = 0;
            __threadfence();
            atomicAdd(&g_bargen, 1u);
        } else {
            while (*(volatile unsigned*)&g_bargen == gen) { }
            __threadfence();
        }
    }
    __syncthreads();
}

__device__ __forceinline__ float block_rsum(float v, float* red) {
    int lane = threadIdx.x & 31, wid = threadIdx.x >> 5;
    #pragma unroll
    for (int o = 16; o; o >>= 1) v += __shfl_xor_sync(~0u, v, o);
    if (lane == 0) red[wid] = v;
    __syncthreads();
    if (threadIdx.x == 0) {
        float t = 0.f;
        #pragma unroll
        for (int i = 0; i < 32; i++) t += red[i];
        red[0] = t;
    }
    __syncthreads();
    float r = red[0];
    __syncthreads();
    return r;
}
__device__ __forceinline__ float block_rmax(float v, float* red) {
    int lane = threadIdx.x & 31, wid = threadIdx.x >> 5;
    #pragma unroll
    for (int o = 16; o; o >>= 1) v = fmaxf(v, __shfl_xor_sync(~0u, v, o));
    if (lane == 0) red[wid] = v;
    __syncthreads();
    if (threadIdx.x == 0) {
        float t = red[0];
        #pragma unroll
        for (int i = 1; i < 32; i++) t = fmaxf(t, red[i]);
        red[0] = t;
    }
    __syncthreads();
    float r = red[0];
    __syncthreads();
    return r;
}
__device__ __forceinline__ float d4(float4 w, float4 a) {
    return w.x * a.x + w.y * a.y + w.z * a.z + w.w * a.w;
}
__device__ __forceinline__ float warp_red(float s) {
    #pragma unroll
    for (int o = 16; o; o >>= 1) s += __shfl_xor_sync(~0u, s, o);
    return s;
}

// ---------------------------------------------------------------------------
__global__ void __launch_bounds__(1024, 1)
decode_k(const float* __restrict__ embed,  const float* __restrict__ q_w,
         const float* __restrict__ k_w,    const float* __restrict__ v_w,
         const float* __restrict__ o_w,    const float* __restrict__ gate_w,
         const float* __restrict__ up_w,   const float* __restrict__ down_w,
         const float* __restrict__ ln1_w,  const float* __restrict__ ln2_w,
         const float* __restrict__ norm_w, const float* __restrict__ lm_head,
         const float* __restrict__ kv,     const float* __restrict__ cosc,
         const float* __restrict__ sinc,   const int* __restrict__ input_ids,
         const int* __restrict__ pos_ids,  float* __restrict__ out) {
    extern __shared__ __align__(16) float smem[];
    float* xs = smem;                       // [1024]
    float* un = smem + 1024;                // [2816] union: xm | attention bufs
    float* xm = un;
    float* sc = un;                         // [256]
    float* qs = un + 256;                   // [64]
    float* kn = un + 320;                   // [64]
    float* vn = un + 384;                   // [64]
    float* part = un + 448;                 // [32*64]
    float* red  = smem + 3840;              // [32]
    int*   redi = (int*)(smem + 3872);      // [32]
    unsigned long long* mbars = (unsigned long long*)(smem + 3904); // [16]
    float* part2 = smem + 3936;             // [32] split-row partials
    float* slab  = smem + 3968;             // 52224 floats (204KB)
    char*  slabB = (char*)slab;

    const int tid = threadIdx.x, lane = tid & 31, wid = tid >> 5;
    const int bid = blockIdx.x;

    const int r0q = (QKV_R * bid) / NBLOCKS, r1q = (QKV_R * (bid + 1)) / NBLOCKS;
    const int r0o = (H * bid) / NBLOCKS,     r1o = (H * (bid + 1)) / NBLOCKS;
    const int r0g = (GU_R * bid) / NBLOCKS,  r1g = (GU_R * (bid + 1)) / NBLOCKS;
    const int r0L = (VOCAB * bid) / NBLOCKS, r1L = (VOCAB * (bid + 1)) / NBLOCKS;
    const int nq = r1q - r0q, no = r1o - r0o, ng = r1g - r0g;

    unsigned seqI = 0, seqW = 0;

    if (tid < 16) mbar_init(s2u(mbars + tid));
    __syncthreads();
    asm volatile("fence.proxy.async.shared::cta;" ::: "memory");

    if (bid == 0) g_hid[tid] = embed[(size_t)input_ids[0] * H + tid];

    // issue qkv for layer 0 (single mbar segment, split sources)
    if (tid == 0) {
        uint32_t mb = s2u(mbars + (seqI & 15));
        mbar_expect(mb, (uint32_t)nq * 4096u);
        int r = r0q;
        while (r < r1q) {
            const float* src; int lim;
            if (r < H)            { src = q_w + (size_t)r * H; lim = min(r1q, H); }
            else if (r < H + 256) { src = k_w + (size_t)(r - H) * H; lim = min(r1q, H + 256); }
            else                  { src = v_w + (size_t)(r - H - 256) * H; lim = r1q; }
            bulk_cp(s2u(slabB + QKVB + (uint32_t)(r - r0q) * 4096u), src,
                    (uint32_t)(lim - r) * 4096u, mb);
            r = lim;
        }
    }
    seqI++;
    grid_sync();

    const int pos = pos_ids[0];
    const int cl = (pos + ACHUNKS) >> 3;

    for (int l = 0; l < LAYERS; l++) {
        // ===== S1: issue gu copy (hidden behind attention); rms1; qkv split-2 =====
        // gu region [0, ng*4096) is free: last layer's down compute finished pre-sync.
        #pragma unroll 1
        for (int c = 0; c < 4; c++) {
            int a = (ng * c) / 4, b = (ng * (c + 1)) / 4;   // local rows
            if (tid == 0) {
                uint32_t mb = s2u(mbars + (seqI & 15));
                mbar_expect(mb, (uint32_t)(b - a) * 4096u);
                int i = a;
                while (i < b) {
                    int u = r0g + i;
                    const float* src; int lim;
                    if (u < INTER) { src = gate_w + (size_t)l * INTER * H + (size_t)u * H;
                                     lim = min(b, INTER - r0g); }
                    else           { src = up_w + (size_t)l * INTER * H + (size_t)(u - INTER) * H;
                                     lim = b; }
                    bulk_cp(s2u(slabB + (uint32_t)i * 4096u), src,
                            (uint32_t)(lim - i) * 4096u, mb);
                    i = lim;
                }
            }
            seqI++;
        }

        float hv = g_hid[tid];
        xs[tid] = hv * ln1_w[(size_t)l * H + tid];
        float ssq = block_rsum(hv * hv, red);
        float rs = rsqrtf(ssq / (float)H + EPS);

        wait_chunk(seqW, mbars);     // qkv slab ready
        {
            const float4* x4 = (const float4*)xs;
            if (wid < 2 * nq) {      // split-2: 2 units per row
                int lr = wid >> 1, half = wid & 1;
                const float4* w4 = (const float4*)(slabB + QKVB + (uint32_t)lr * 4096u);
                float s = 0.f;
                #pragma unroll
                for (int k = 0; k < 4; k++) {
                    int i = half * 128 + lane + k * 32;
                    s += d4(w4[i], x4[i]);
                }
                s = warp_red(s);
                if (lane == 0) part2[wid] = s;
            }
            __syncthreads();
            if (tid < nq) g_qkv[r0q + tid] = (part2[2 * tid] + part2[2 * tid + 1]) * rs;
        }
        grid_sync();

        // ===== S2: attention (gu copy streams in background) =====
        if (bid < NH * ACHUNKS) {
            int head = bid >> 3, ch = bid & (ACHUNKS - 1), kvh = head >> 2;
            int j0 = ch * cl;
            int j1 = min(j0 + cl, pos + 1);
            int n = j1 - j0;

            if (tid < HD) {
                float c  = cosc[(size_t)pos * HD + tid];
                float sn = sinc[(size_t)pos * HD + tid];
                float q0 = g_qkv[head * HD + tid];
                float qr = g_qkv[head * HD + ((tid < HD / 2) ? tid + HD / 2 : tid - HD / 2)];
                if (tid < HD / 2) qr = -qr;
                qs[tid] = q0 * c + qr * sn;
                float k0 = g_qkv[H + kvh * HD + tid];
                float kr = g_qkv[H + kvh * HD + ((tid < HD / 2) ? tid + HD / 2 : tid - HD / 2)];
                if (tid < HD / 2) kr = -kr;
                kn[tid] = k0 * c + kr * sn;
                vn[tid] = g_qkv[H + KVH * HD + kvh * HD + tid];
            }
            __syncthreads();

            const float* K = kv + (size_t)l * KVH * CTX * HD + (size_t)kvh * CTX * HD;
            const float* V = kv + (size_t)(LAYERS + l) * KVH * CTX * HD + (size_t)kvh * CTX * HD;
            const float4* q4 = (const float4*)qs;

            int half = lane >> 4, hl = lane & 15;
            for (int jb = j0 + wid * 2; jb < j1; jb += 64) {
                int j = jb + half;
                bool valid = (j < j1);
                const float4* k4;
                if (!valid)        k4 = (const float4*)kn;
                else if (j == pos) k4 = (const float4*)kn;
                else               k4 = (const float4*)(K + (size_t)j * HD);
                float4 a = q4[hl], b = k4[hl];
                float s = a.x * b.x + a.y * b.y + a.z * b.z + a.w * b.w;
                #pragma unroll
                for (int o = 8; o; o >>= 1) s += __shfl_xor_sync(~0u, s, o);
                if (hl == 0 && valid) sc[j - j0] = s * 0.125f;
            }
            __syncthreads();

            float m = -1e30f;
            if (tid < n) m = sc[tid];
            float M = block_rmax(m, red);
            float e = 0.f;
            if (tid < n) { e = __expf(sc[tid] - M); sc[tid] = e; }
            float S = block_rsum(e, red);

            float a0 = 0.f, a1 = 0.f;
            for (int j = j0 + wid; j < j1; j += 32) {
                float p = sc[j - j0];
                const float* Vr = (j == pos) ? (const float*)vn : V + (size_t)j * HD;
                a0 += p * Vr[lane];
                a1 += p * Vr[lane + 32];
            }
            part[wid * HD + lane]      = a0;
            part[wid * HD + lane + 32] = a1;
            __syncthreads();
            if (tid == 0) { g_am[head][ch] = (n > 0) ? M : -1e30f; g_as[head][ch] = S; }
            if (tid < HD) {
                float t = 0.f;
                #pragma unroll
                for (int w = 0; w < 32; w++) t += part[w * HD + tid];
                g_ao[head][ch][tid] = t;
            }
        }
        grid_sync();

        // ===== S3: combine attention -> xs; o-proj direct LDG split-4 =====
        {
            int head = tid >> 6, d = tid & (HD - 1);
            float M = -1e30f;
            #pragma unroll
            for (int c = 0; c < ACHUNKS; c++) M = fmaxf(M, g_am[head][c]);
            float S = 0.f, o = 0.f;
            #pragma unroll
            for (int c = 0; c < ACHUNKS; c++) {
                float e = __expf(g_am[head][c] - M);
                S += g_as[head][c] * e;
                o += g_ao[head][c][d] * e;
            }
            xs[tid] = o / S;
        }
        __syncthreads();

        {
            const float4* x4 = (const float4*)xs;
            if (wid < 4 * no) {       // split-4: 4 units per row
                int lr = wid >> 2, q4i = wid & 3;
                const float4* w4 = (const float4*)(o_w + (size_t)l * H * H
                                                   + (size_t)(r0o + lr) * H);
                float s = 0.f;
                #pragma unroll
                for (int k = 0; k < 2; k++) {
                    int i = q4i * 64 + lane + k * 32;
                    s += d4(w4[i], x4[i]);
                }
                s = warp_red(s);
                if (lane == 0) part2[wid] = s;
            }
            __syncthreads();
            if (tid < no)
                g_hid[r0o + tid] += part2[4 * tid] + part2[4 * tid + 1]
                                  + part2[4 * tid + 2] + part2[4 * tid + 3];
        }
        grid_sync();

        // ===== S4: rms2; wait gu chunks + compute; issue down =====
        hv = g_hid[tid];
        xs[tid] = hv * ln2_w[(size_t)l * H + tid];
        ssq = block_rsum(hv * hv, red);
        float rs2 = rsqrtf(ssq / (float)H + EPS);

        {
            const float4* x4 = (const float4*)xs;
            #pragma unroll 1
            for (int c = 0; c < 4; c++) {
                int a = (ng * c) / 4, b = (ng * (c + 1)) / 4;
                wait_chunk(seqW, mbars);
                for (int i = a + wid; i < b; i += 32) {
                    const float4* w4 = (const float4*)(slabB + (uint32_t)i * 4096u);
                    float s = 0.f;
                    #pragma unroll
                    for (int k = 0; k < 8; k++) { int ii = lane + k * 32; s += d4(w4[ii], x4[ii]); }
                    s = warp_red(s);
                    if (lane == 0) g_gu[r0g + i] = s * rs2;
                }
            }
        }
        __syncthreads();     // all gu reads done before down copy overwrites [0, no*11264)
        #pragma unroll 1
        for (int c = 0; c < 2; c++) {
            int a = r0o + (no * c) / 2, b = r0o + (no * (c + 1)) / 2;
            issue_seg(seqI, mbars, tid, slabB, (uint32_t)(a - r0o) * 11264u,
                      down_w + (size_t)l * H * INTER + (size_t)a * INTER,
                      (uint32_t)(b - a) * 11264u);
        }
        grid_sync();

        // ===== S5: issue next qkv; build xm; wait down + compute split-4 =====
        if (l + 1 < LAYERS) {
            if (tid == 0) {
                uint32_t mb = s2u(mbars + (seqI & 15));
                mbar_expect(mb, (uint32_t)nq * 4096u);
                int r = r0q;
                while (r < r1q) {
                    const float* src; int lim;
                    if (r < H)            { src = q_w + (size_t)(l + 1) * H * H + (size_t)r * H; lim = min(r1q, H); }
                    else if (r < H + 256) { src = k_w + (size_t)(l + 1) * 256 * H + (size_t)(r - H) * H; lim = min(r1q, H + 256); }
                    else                  { src = v_w + (size_t)(l + 1) * 256 * H + (size_t)(r - H - 256) * H; lim = r1q; }
                    bulk_cp(s2u(slabB + QKVB + (uint32_t)(r - r0q) * 4096u), src,
                            (uint32_t)(lim - r) * 4096u, mb);
                    r = lim;
                }
            }
            seqI++;
        }
        for (int i = tid; i < INTER; i += 1024) {
            float g = g_gu[i];
            float u = g_gu[INTER + i];
            xm[i] = (g / (1.f + __expf(-g))) * u;
        }
        __syncthreads();

        #pragma unroll 1
        for (int c = 0; c < 2; c++) {
            int a = (no * c) / 2, b = (no * (c + 1)) / 2;   // local rows
            int nr = b - a;
            wait_chunk(seqW, mbars);
            if (wid < 4 * nr) {       // split-4 per row (704 floats each)
                int lr = a + (wid >> 2), q4i = wid & 3;
                const float4* w4 = (const float4*)(slabB + (uint32_t)lr * 11264u
                                                   + (uint32_t)q4i * 2816u);
                const float4* xm4 = (const float4*)(xm + q4i * 704);
                float s = 0.f;
                for (int i = lane; i < 176; i += 32) s += d4(w4[i], xm4[i]);
                s = warp_red(s);
                if (lane == 0) part2[wid] = s;
            }
            __syncthreads();
            if (tid < nr)
                g_hid[r0o + a + tid] += part2[4 * tid] + part2[4 * tid + 1]
                                      + part2[4 * tid + 2] + part2[4 * tid + 3];
            __syncthreads();
        }
        grid_sync();
    }

    // =========== final norm + streamed lm_head + argmax ===========
    {
        float hv = g_hid[tid];
        xs[tid] = hv * norm_w[tid];
        float ssq = block_rsum(hv * hv, red);
        float rsf = rsqrtf(ssq / (float)H + EPS);

        int nL = r1L - r0L;
        int nch = (nL + 11) / 12;
        for (int c = 0; c < nch && c < 4; c++) {
            int a = r0L + c * 12, b = min(a + 12, r1L);
            issue_seg(seqI, mbars, tid, slabB, (uint32_t)(c & 3) * LMB,
                      lm_head + (size_t)a * H, (uint32_t)(b - a) * 4096u);
        }

        float bv = -1e30f;
        int   bi = 0x7fffffff;
        const float4* x4 = (const float4*)xs;
        #pragma unroll 1
        for (int c = 0; c < nch; c++) {
            wait_chunk(seqW, mbars);
            int a = r0L + c * 12, b = min(a + 12, r1L);
            const char* base = slabB + (size_t)(c & 3) * LMB;
            for (int r = a + wid; r < b; r += 32) {
                const float4* w4 = (const float4*)(base + (size_t)(r - a) * 4096);
                float s = 0.f;
                #pragma unroll
                for (int k = 0; k < 8; k++) { int i = lane + k * 32; s += d4(w4[i], x4[i]); }
                s = warp_red(s) * rsf;
                if (s > bv || (s == bv && r < bi)) { bv = s; bi = r; }
            }
            __syncthreads();
            if (c + 4 < nch) {
                int a2 = r0L + (c + 4) * 12, b2 = min(a2 + 12, r1L);
                issue_seg(seqI, mbars, tid, slabB, (uint32_t)((c + 4) & 3) * LMB,
                          lm_head + (size_t)a2 * H, (uint32_t)(b2 - a2) * 4096u);
            }
        }

        if (lane == 0) { red[wid] = bv; redi[wid] = bi; }
        __syncthreads();
        if (tid == 0) {
            float b = red[0]; int ii = redi[0];
            #pragma unroll
            for (int i = 1; i < 32; i++)
                if (red[i] > b || (red[i] == b && redi[i] < ii)) { b = red[i]; ii = redi[i]; }
            g_lmv[bid] = b;
            g_lmi[bid] = ii;
        }
        grid_sync();
        if (bid == 0 && tid == 0) {
            float b = g_lmv[0]; int ii = g_lmi[0];
            for (int i = 1; i < NBLOCKS; i++) {
                float v = g_lmv[i]; int id = g_lmi[i];
                if (v > b || (v == b && id < ii)) { b = v; ii = id; }
            }
            out[0] = (float)ii;
            out[1] = b;
        }
    }
}

// ---------------------------------------------------------------------------
extern "C" void kernel_launch(void* const* d_in, const int* in_sizes, int n_in,
                              void* d_out, int out_size) {
    const float* embed   = (const float*)d_in[0];
    const float* q_w     = (const float*)d_in[1];
    const float* k_w     = (const float*)d_in[2];
    const float* v_w     = (const float*)d_in[3];
    const float* o_w     = (const float*)d_in[4];
    const float* gate_w  = (const float*)d_in[5];
    const float* up_w    = (const float*)d_in[6];
    const float* down_w  = (const float*)d_in[7];
    const float* ln1_w   = (const float*)d_in[8];
    const float* ln2_w   = (const float*)d_in[9];
    const float* norm_w  = (const float*)d_in[10];
    const float* lm_head = (const float*)d_in[11];
    const float* kv      = (const float*)d_in[12];
    const float* cosc    = (const float*)d_in[13];
    const float* sinc    = (const float*)d_in[14];
    const int* input_ids = (const int*)d_in[17];
    const int* pos_ids   = (const int*)d_in[18];

    static bool attr_set = false;
    if (!attr_set) {
        cudaFuncSetAttribute(decode_k, cudaFuncAttributeMaxDynamicSharedMemorySize,
                             SMEM_FLOATS * 4);
        attr_set = true;
    }

    decode_k<<<NBLOCKS, 1024, SMEM_FLOATS * 4>>>(
        embed, q_w, k_w, v_w, o_w, gate_w, up_w, down_w,
        ln1_w, ln2_w, norm_w, lm_head, kv, cosc, sinc,
        input_ids, pos_ids, (float*)d_out);
}

// round 10
// speedup vs baseline: 1.1808x; 1.0937x over previous
#include <cuda_runtime.h>
#include <math.h>
#include <stdint.h>

#define LAYERS 8
#define H      1024
#define NH     16
#define KVH    4
#define HD     64
#define INTER  2816
#define VOCAB  32000
#define CTX    2048
#define EPS    1e-5f

#define NBLOCKS 148
#define ACHUNKS 8
#define QKV_R   1536
#define GU_R    5632
#define QKVB    159744u      // qkv/o region byte offset in slab (39 rows * 4KB)
#define LMB     49152u       // lm tile stride (12 rows * 4KB)
#define SMEM_FLOATS 55136    // 220544 bytes dynamic smem

// ---------------------------------------------------------------------------
__device__ __align__(16) float g_hid[H];
__device__ __align__(16) float g_qkv[QKV_R];
__device__ __align__(16) float g_gu[GU_R];
__device__ float g_am[NH][ACHUNKS];
__device__ float g_as[NH][ACHUNKS];
__device__ __align__(16) float g_ao[NH][ACHUNKS][HD];
__device__ float    g_lmv[NBLOCKS];
__device__ int      g_lmi[NBLOCKS];
__device__ unsigned g_barcnt;
__device__ unsigned g_bargen;

// ---------------------------------------------------------------------------
__device__ __forceinline__ uint32_t s2u(const void* p) {
    return (uint32_t)__cvta_generic_to_shared(p);
}
__device__ __forceinline__ void mbar_init(uint32_t mb) {
    asm volatile("mbarrier.init.shared.b64 [%0], %1;" :: "r"(mb), "r"(1u) : "memory");
}
__device__ __forceinline__ void mbar_expect(uint32_t mb, uint32_t bytes) {
    asm volatile("mbarrier.arrive.expect_tx.shared.b64 _, [%0], %1;"
                 :: "r"(mb), "r"(bytes) : "memory");
}
__device__ __forceinline__ void mbar_wait(uint32_t mb, unsigned parity) {
    asm volatile(
        "{\n\t.reg .pred P;\n\t"
        "LAB_W%=:\n\t"
        "mbarrier.try_wait.parity.acquire.cta.shared::cta.b64 P, [%0], %1, 0x989680;\n\t"
        "@P bra LAB_D%=;\n\t"
        "bra LAB_W%=;\n\t"
        "LAB_D%=:\n\t}"
        :: "r"(mb), "r"(parity) : "memory");
}
__device__ __forceinline__ void bulk_cp(uint32_t dst, const float* src,
                                        uint32_t bytes, uint32_t mb) {
    asm volatile(
        "cp.async.bulk.shared::cluster.global.mbarrier::complete_tx::bytes [%0], [%1], %2, [%3];"
        :: "r"(dst), "l"(src), "r"(bytes), "r"(mb) : "memory");
}

// ---------------------------------------------------------------------------
__device__ __forceinline__ void grid_sync() {
    __syncthreads();
    if (threadIdx.x == 0) {
        __threadfence();
        unsigned gen = *(volatile unsigned*)&g_bargen;
        if (atomicAdd(&g_barcnt, 1u) == NBLOCKS - 1) {
            g_barcnt = 0;
            __threadfence();
            atomicAdd(&g_bargen, 1u);
        } else {
            while (*(volatile unsigned*)&g_bargen == gen) { }
            __threadfence();
        }
    }
    __syncthreads();
}

__device__ __forceinline__ float block_rsum(float v, float* red) {
    int lane = threadIdx.x & 31, wid = threadIdx.x >> 5;
    #pragma unroll
    for (int o = 16; o; o >>= 1) v += __shfl_xor_sync(~0u, v, o);
    if (lane == 0) red[wid] = v;
    __syncthreads();
    if (threadIdx.x == 0) {
        float t = 0.f;
        #pragma unroll
        for (int i = 0; i < 32; i++) t += red[i];
        red[0] = t;
    }
    __syncthreads();
    float r = red[0];
    __syncthreads();
    return r;
}
__device__ __forceinline__ float block_rmax(float v, float* red) {
    int lane = threadIdx.x & 31, wid = threadIdx.x >> 5;
    #pragma unroll
    for (int o = 16; o; o >>= 1) v = fmaxf(v, __shfl_xor_sync(~0u, v, o));
    if (lane == 0) red[wid] = v;
    __syncthreads();
    if (threadIdx.x == 0) {
        float t = red[0];
        #pragma unroll
        for (int i = 1; i < 32; i++) t = fmaxf(t, red[i]);
        red[0] = t;
    }
    __syncthreads();
    float r = red[0];
    __syncthreads();
    return r;
}
__device__ __forceinline__ float d4(float4 w, float4 a) {
    return w.x * a.x + w.y * a.y + w.z * a.z + w.w * a.w;
}
__device__ __forceinline__ float warp_red(float s) {
    #pragma unroll
    for (int o = 16; o; o >>= 1) s += __shfl_xor_sync(~0u, s, o);
    return s;
}

// ---------------------------------------------------------------------------
__global__ void __launch_bounds__(1024, 1)
decode_k(const float* __restrict__ embed,  const float* __restrict__ q_w,
         const float* __restrict__ k_w,    const float* __restrict__ v_w,
         const float* __restrict__ o_w,    const float* __restrict__ gate_w,
         const float* __restrict__ up_w,   const float* __restrict__ down_w,
         const float* __restrict__ ln1_w,  const float* __restrict__ ln2_w,
         const float* __restrict__ norm_w, const float* __restrict__ lm_head,
         const float* __restrict__ kv,     const float* __restrict__ cosc,
         const float* __restrict__ sinc,   const int* __restrict__ input_ids,
         const int* __restrict__ pos_ids,  float* __restrict__ out) {
    extern __shared__ __align__(16) float smem[];
    float* xs = smem;                       // [1024]
    float* un = smem + 1024;                // [2816] union: xm | attention bufs
    float* xm = un;
    float* sc = un;                         // [256]
    float* qs = un + 256;                   // [64]
    float* kn = un + 320;                   // [64]
    float* vn = un + 384;                   // [64]
    float* part = un + 448;                 // [32*64]
    float* red  = smem + 3840;              // [32]
    int*   redi = (int*)(smem + 3872);      // [32]
    unsigned long long* mbars = (unsigned long long*)(smem + 3904); // [16]
    float* slab  = smem + 3936;             // 51200 floats (200KB)
    char*  slabB = (char*)slab;

    const int tid = threadIdx.x, lane = tid & 31, wid = tid >> 5;
    const int bid = blockIdx.x;

    const int r0q = (QKV_R * bid) / NBLOCKS, r1q = (QKV_R * (bid + 1)) / NBLOCKS;
    const int r0o = (H * bid) / NBLOCKS,     r1o = (H * (bid + 1)) / NBLOCKS;
    const int r0g = (GU_R * bid) / NBLOCKS,  r1g = (GU_R * (bid + 1)) / NBLOCKS;
    const int r0L = (VOCAB * bid) / NBLOCKS, r1L = (VOCAB * (bid + 1)) / NBLOCKS;
    const int nq = r1q - r0q, no = r1o - r0o, ng = r1g - r0g;

    // named mbarriers: 0=qkv 1=gu 2=o 3=down 4..7=lm tiles
    const uint32_t mbQ = s2u(mbars + 0), mbG = s2u(mbars + 1);
    const uint32_t mbO = s2u(mbars + 2), mbD = s2u(mbars + 3);

    if (tid < 16) mbar_init(s2u(mbars + tid));
    __syncthreads();
    asm volatile("fence.proxy.async.shared::cta;" ::: "memory");

    if (bid == 0) g_hid[tid] = embed[(size_t)input_ids[0] * H + tid];

    // prologue: issue qkv for layer 0 into QKVB region
    if (tid == 0) {
        mbar_expect(mbQ, (uint32_t)nq * 4096u);
        int r = r0q;
        while (r < r1q) {
            const float* src; int lim;
            if (r < H)            { src = q_w + (size_t)r * H; lim = min(r1q, H); }
            else if (r < H + 256) { src = k_w + (size_t)(r - H) * H; lim = min(r1q, H + 256); }
            else                  { src = v_w + (size_t)(r - H - 256) * H; lim = r1q; }
            bulk_cp(s2u(slabB + QKVB + (uint32_t)(r - r0q) * 4096u), src,
                    (uint32_t)(lim - r) * 4096u, mbQ);
            r = lim;
        }
    }
    grid_sync();

    const int pos = pos_ids[0];
    const int cl = (pos + ACHUNKS) >> 3;

    for (int l = 0; l < LAYERS; l++) {
        const unsigned par = (unsigned)(l & 1);

        // ===== S1: issue gu (early!); rms1; wait+compute qkv; issue o =====
        // gu region [0, ng*4096) is free: prev layer's down compute finished pre-sync.
        if (tid == 0) {
            mbar_expect(mbG, (uint32_t)ng * 4096u);
            int i = 0;
            while (i < ng) {
                int u = r0g + i;
                const float* src; int lim;
                if (u < INTER) { src = gate_w + (size_t)l * INTER * H + (size_t)u * H;
                                 lim = min(ng, INTER - r0g); }
                else           { src = up_w + (size_t)l * INTER * H + (size_t)(u - INTER) * H;
                                 lim = ng; }
                bulk_cp(s2u(slabB + (uint32_t)i * 4096u), src,
                        (uint32_t)(lim - i) * 4096u, mbG);
                i = lim;
            }
        }

        float hv = g_hid[tid];
        xs[tid] = hv * ln1_w[(size_t)l * H + tid];
        float ssq = block_rsum(hv * hv, red);
        float rs = rsqrtf(ssq / (float)H + EPS);

        mbar_wait(mbQ, par);
        {
            const float4* x4 = (const float4*)xs;
            for (int r = r0q + wid; r < r1q; r += 32) {
                const float4* w4 = (const float4*)(slabB + QKVB + (uint32_t)(r - r0q) * 4096u);
                float s = 0.f;
                #pragma unroll
                for (int k = 0; k < 8; k++) { int i = lane + k * 32; s += d4(w4[i], x4[i]); }
                s = warp_red(s);
                if (lane == 0) g_qkv[r] = s * rs;
            }
        }
        __syncthreads();   // all warps done reading qkv region before o copy overwrites
        if (tid == 0) {
            mbar_expect(mbO, (uint32_t)no * 4096u);
            bulk_cp(s2u(slabB + QKVB), o_w + (size_t)l * H * H + (size_t)r0o * H,
                    (uint32_t)no * 4096u, mbO);
        }
        grid_sync();

        // ===== S2: attention (gu + o copies stream in background) =====
        if (bid < NH * ACHUNKS) {
            int head = bid >> 3, ch = bid & (ACHUNKS - 1), kvh = head >> 2;
            int j0 = ch * cl;
            int j1 = min(j0 + cl, pos + 1);
            int n = j1 - j0;

            if (tid < HD) {
                float c  = cosc[(size_t)pos * HD + tid];
                float sn = sinc[(size_t)pos * HD + tid];
                float q0 = g_qkv[head * HD + tid];
                float qr = g_qkv[head * HD + ((tid < HD / 2) ? tid + HD / 2 : tid - HD / 2)];
                if (tid < HD / 2) qr = -qr;
                qs[tid] = q0 * c + qr * sn;
                float k0 = g_qkv[H + kvh * HD + tid];
                float kr = g_qkv[H + kvh * HD + ((tid < HD / 2) ? tid + HD / 2 : tid - HD / 2)];
                if (tid < HD / 2) kr = -kr;
                kn[tid] = k0 * c + kr * sn;
                vn[tid] = g_qkv[H + KVH * HD + kvh * HD + tid];
            }
            __syncthreads();

            const float* K = kv + (size_t)l * KVH * CTX * HD + (size_t)kvh * CTX * HD;
            const float* V = kv + (size_t)(LAYERS + l) * KVH * CTX * HD + (size_t)kvh * CTX * HD;
            const float4* q4 = (const float4*)qs;

            int half = lane >> 4, hl = lane & 15;
            for (int jb = j0 + wid * 2; jb < j1; jb += 64) {
                int j = jb + half;
                bool valid = (j < j1);
                const float4* k4;
                if (!valid)        k4 = (const float4*)kn;
                else if (j == pos) k4 = (const float4*)kn;
                else               k4 = (const float4*)(K + (size_t)j * HD);
                float4 a = q4[hl], b = k4[hl];
                float s = a.x * b.x + a.y * b.y + a.z * b.z + a.w * b.w;
                #pragma unroll
                for (int o = 8; o; o >>= 1) s += __shfl_xor_sync(~0u, s, o);
                if (hl == 0 && valid) sc[j - j0] = s * 0.125f;
            }
            __syncthreads();

            float m = -1e30f;
            if (tid < n) m = sc[tid];
            float M = block_rmax(m, red);
            float e = 0.f;
            if (tid < n) { e = __expf(sc[tid] - M); sc[tid] = e; }
            float S = block_rsum(e, red);

            float a0 = 0.f, a1 = 0.f;
            for (int j = j0 + wid; j < j1; j += 32) {
                float p = sc[j - j0];
                const float* Vr = (j == pos) ? (const float*)vn : V + (size_t)j * HD;
                a0 += p * Vr[lane];
                a1 += p * Vr[lane + 32];
            }
            part[wid * HD + lane]      = a0;
            part[wid * HD + lane + 32] = a1;
            __syncthreads();
            if (tid == 0) { g_am[head][ch] = (n > 0) ? M : -1e30f; g_as[head][ch] = S; }
            if (tid < HD) {
                float t = 0.f;
                #pragma unroll
                for (int w = 0; w < 32; w++) t += part[w * HD + tid];
                g_ao[head][ch][tid] = t;
            }
        }
        grid_sync();

        // ===== S3: combine attention -> xs; wait+compute o =====
        {
            int head = tid >> 6, d = tid & (HD - 1);
            float M = -1e30f;
            #pragma unroll
            for (int c = 0; c < ACHUNKS; c++) M = fmaxf(M, g_am[head][c]);
            float S = 0.f, o = 0.f;
            #pragma unroll
            for (int c = 0; c < ACHUNKS; c++) {
                float e = __expf(g_am[head][c] - M);
                S += g_as[head][c] * e;
                o += g_ao[head][c][d] * e;
            }
            xs[tid] = o / S;
        }
        __syncthreads();

        mbar_wait(mbO, par);
        {
            const float4* x4 = (const float4*)xs;
            for (int r = r0o + wid; r < r1o; r += 32) {
                const float4* w4 = (const float4*)(slabB + QKVB + (uint32_t)(r - r0o) * 4096u);
                float s = 0.f;
                #pragma unroll
                for (int k = 0; k < 8; k++) { int i = lane + k * 32; s += d4(w4[i], x4[i]); }
                s = warp_red(s);
                if (lane == 0) g_hid[r] += s;
            }
        }
        grid_sync();

        // ===== S4: rms2; wait+compute gu (copy has been streaming since S1); issue down =====
        hv = g_hid[tid];
        xs[tid] = hv * ln2_w[(size_t)l * H + tid];
        ssq = block_rsum(hv * hv, red);
        float rs2 = rsqrtf(ssq / (float)H + EPS);

        mbar_wait(mbG, par);
        {
            const float4* x4 = (const float4*)xs;
            for (int i = wid; i < ng; i += 32) {
                const float4* w4 = (const float4*)(slabB + (uint32_t)i * 4096u);
                float s = 0.f;
                #pragma unroll
                for (int k = 0; k < 8; k++) { int ii = lane + k * 32; s += d4(w4[ii], x4[ii]); }
                s = warp_red(s);
                if (lane == 0) g_gu[r0g + i] = s * rs2;
            }
        }
        __syncthreads();   // all gu reads done before down copy overwrites [0, no*11264)
        if (tid == 0) {
            mbar_expect(mbD, (uint32_t)no * 11264u);
            bulk_cp(s2u(slabB), down_w + (size_t)l * H * INTER + (size_t)r0o * INTER,
                    (uint32_t)no * 11264u, mbD);
        }
        grid_sync();

        // ===== S5: issue next qkv; build xm; wait+compute down =====
        if (l + 1 < LAYERS) {
            if (tid == 0) {
                mbar_expect(mbQ, (uint32_t)nq * 4096u);
                int r = r0q;
                while (r < r1q) {
                    const float* src; int lim;
                    if (r < H)            { src = q_w + (size_t)(l + 1) * H * H + (size_t)r * H; lim = min(r1q, H); }
                    else if (r < H + 256) { src = k_w + (size_t)(l + 1) * 256 * H + (size_t)(r - H) * H; lim = min(r1q, H + 256); }
                    else                  { src = v_w + (size_t)(l + 1) * 256 * H + (size_t)(r - H - 256) * H; lim = r1q; }
                    bulk_cp(s2u(slabB + QKVB + (uint32_t)(r - r0q) * 4096u), src,
                            (uint32_t)(lim - r) * 4096u, mbQ);
                    r = lim;
                }
            }
        }
        for (int i = tid; i < INTER; i += 1024) {
            float g = g_gu[i];
            float u = g_gu[INTER + i];
            xm[i] = (g / (1.f + __expf(-g))) * u;
        }
        __syncthreads();

        mbar_wait(mbD, par);
        {
            const float4* xm4 = (const float4*)xm;
            for (int r = r0o + wid; r < r1o; r += 32) {
                const float4* w4 = (const float4*)(slabB + (uint32_t)(r - r0o) * 11264u);
                float s = 0.f;
                for (int i = lane; i < INTER / 4; i += 32) s += d4(w4[i], xm4[i]);
                s = warp_red(s);
                if (lane == 0) g_hid[r] += s;
            }
        }
        grid_sync();
    }

    // =========== final norm + streamed lm_head + argmax ===========
    {
        float hv = g_hid[tid];
        xs[tid] = hv * norm_w[tid];
        float ssq = block_rsum(hv * hv, red);
        float rsf = rsqrtf(ssq / (float)H + EPS);

        int nL = r1L - r0L;
        int nch = (nL + 11) / 12;
        for (int c = 0; c < nch && c < 4; c++) {
            int a = r0L + c * 12, b = min(a + 12, r1L);
            if (tid == 0) {
                uint32_t mb = s2u(mbars + 4 + c);
                mbar_expect(mb, (uint32_t)(b - a) * 4096u);
                bulk_cp(s2u(slabB + (uint32_t)c * LMB), lm_head + (size_t)a * H,
                        (uint32_t)(b - a) * 4096u, mb);
            }
        }

        float bv = -1e30f;
        int   bi = 0x7fffffff;
        const float4* x4 = (const float4*)xs;
        #pragma unroll 1
        for (int c = 0; c < nch; c++) {
            mbar_wait(s2u(mbars + 4 + (c & 3)), (unsigned)((c >> 2) & 1));
            int a = r0L + c * 12, b = min(a + 12, r1L);
            const char* base = slabB + (uint32_t)(c & 3) * LMB;
            for (int r = a + wid; r < b; r += 32) {
                const float4* w4 = (const float4*)(base + (uint32_t)(r - a) * 4096u);
                float s = 0.f;
                #pragma unroll
                for (int k = 0; k < 8; k++) { int i = lane + k * 32; s += d4(w4[i], x4[i]); }
                s = warp_red(s) * rsf;
                if (s > bv || (s == bv && r < bi)) { bv = s; bi = r; }
            }
            __syncthreads();
            if (c + 4 < nch) {
                int a2 = r0L + (c + 4) * 12, b2 = min(a2 + 12, r1L);
                if (tid == 0) {
                    uint32_t mb = s2u(mbars + 4 + (c & 3));
                    mbar_expect(mb, (uint32_t)(b2 - a2) * 4096u);
                    bulk_cp(s2u(slabB + (uint32_t)(c & 3) * LMB), lm_head + (size_t)a2 * H,
                            (uint32_t)(b2 - a2) * 4096u, mb);
                }
            }
        }

        if (lane == 0) { red[wid] = bv; redi[wid] = bi; }
        __syncthreads();
        if (tid == 0) {
            float b = red[0]; int ii = redi[0];
            #pragma unroll
            for (int i = 1; i < 32; i++)
                if (red[i] > b || (red[i] == b && redi[i] < ii)) { b = red[i]; ii = redi[i]; }
            g_lmv[bid] = b;
            g_lmi[bid] = ii;
        }
        grid_sync();
        if (bid == 0 && tid == 0) {
            float b = g_lmv[0]; int ii = g_lmi[0];
            for (int i = 1; i < NBLOCKS; i++) {
                float v = g_lmv[i]; int id = g_lmi[i];
                if (v > b || (v == b && id < ii)) { b = v; ii = id; }
            }
            out[0] = (float)ii;
            out[1] = b;
        }
    }
}

// ---------------------------------------------------------------------------
extern "C" void kernel_launch(void* const* d_in, const int* in_sizes, int n_in,
                              void* d_out, int out_size) {
    const float* embed   = (const float*)d_in[0];
    const float* q_w     = (const float*)d_in[1];
    const float* k_w     = (const float*)d_in[2];
    const float* v_w     = (const float*)d_in[3];
    const float* o_w     = (const float*)d_in[4];
    const float* gate_w  = (const float*)d_in[5];
    const float* up_w    = (const float*)d_in[6];
    const float* down_w  = (const float*)d_in[7];
    const float* ln1_w   = (const float*)d_in[8];
    const float* ln2_w   = (const float*)d_in[9];
    const float* norm_w  = (const float*)d_in[10];
    const float* lm_head = (const float*)d_in[11];
    const float* kv      = (const float*)d_in[12];
    const float* cosc    = (const float*)d_in[13];
    const float* sinc    = (const float*)d_in[14];
    const int* input_ids = (const int*)d_in[17];
    const int* pos_ids   = (const int*)d_in[18];

    static bool attr_set = false;
    if (!attr_set) {
        cudaFuncSetAttribute(decode_k, cudaFuncAttributeMaxDynamicSharedMemorySize,
                             SMEM_FLOATS * 4);
        attr_set = true;
    }

    decode_k<<<NBLOCKS, 1024, SMEM_FLOATS * 4>>>(
        embed, q_w, k_w, v_w, o_w, gate_w, up_w, down_w,
        ln1_w, ln2_w, norm_w, lm_head, kv, cosc, sinc,
        input_ids, pos_ids, (float*)d_out);
}